// round 5
// baseline (speedup 1.0000x reference)
#include <cuda_runtime.h>
#include <math.h>

#define BSZ 1024      // batch (edge events)
#define NND 1024      // nodes
#define DIM 256       // feature dim
#define K3  768       // 3*DIM

// ---------------- scratch (device globals; no allocation) ----------------
__device__ __align__(16) float g_Xsrc[BSZ * K3];
__device__ __align__(16) float g_Xtar[BSZ * K3];
__device__ __align__(16) float g_H0[BSZ * DIM];
__device__ __align__(16) float g_H1[BSZ * DIM];
__device__ __align__(16) float g_sums[NND * DIM];
__device__ __align__(16) float g_cnt[NND];
__device__ __align__(16) float g_GI[NND * K3];
__device__ __align__(16) float g_GH[NND * K3];

// ---------------- gather: build MLP inputs + counts ----------------
// grid=BSZ blocks, 256 threads. Each thread handles one float4 of one segment.
__global__ void gather_kernel(const float* __restrict__ memory,
                              const int* __restrict__ src,
                              const int* __restrict__ tgt,
                              const float* __restrict__ dtv) {
    int b = blockIdx.x;
    int t = threadIdx.x;
    int seg = t >> 6;     // 0..3
    int v   = t & 63;     // float4 index within 256-dim row
    int s = src[b];
    int g = tgt[b];

    float4* Xs4 = reinterpret_cast<float4*>(g_Xsrc) + (size_t)b * (K3 / 4);
    float4* Xt4 = reinterpret_cast<float4*>(g_Xtar) + (size_t)b * (K3 / 4);

    if (seg == 0) {
        float4 m = reinterpret_cast<const float4*>(memory)[(size_t)s * 64 + v];
        Xs4[v] = m;            // src_mem -> Xsrc[0:256]
        Xt4[64 + v] = m;       // src_mem -> Xtar[256:512]
    } else if (seg == 1) {
        float4 m = reinterpret_cast<const float4*>(memory)[(size_t)g * 64 + v];
        Xs4[64 + v] = m;       // tgt_mem -> Xsrc[256:512]
        Xt4[v] = m;            // tgt_mem -> Xtar[0:256]
    } else if (seg == 2) {
        float4 d = reinterpret_cast<const float4*>(dtv)[((size_t)b * NND + s) * 64 + v];
        Xs4[128 + v] = d;      // src_dt -> Xsrc[512:768]
    } else {
        float4 d = reinterpret_cast<const float4*>(dtv)[((size_t)b * NND + g) * 64 + v];
        Xt4[128 + v] = d;      // tgt_dt -> Xtar[512:768]
    }
    if (t == 0) {
        atomicAdd(&g_cnt[s], 1.0f);
        atomicAdd(&g_cnt[g], 1.0f);
    }
}

// ---------------- batched tiled SGEMM ----------------
// C[M,N] = A[M,K] @ W[N,K]^T + bias[N]
// mode: 0 = store, 1 = relu + store, 2 = atomicAdd into g_sums[sidx[row]*DIM + col]
// divA: scale A row r by 1/max(g_cnt[r],1) on load (fused aggregation divide)
// 64x64 tile, BK=16, 256 threads, 4x4 microtile, double-buffered smem,
// float4 global loads, transposed smem for float4 LDS.
struct GemmArgs {
    const float* A;
    const float* W;
    const float* bias;
    float* C;
    const int* sidx;
    int divA;
};

__global__ __launch_bounds__(256) void sgemm_kernel(GemmArgs a0, GemmArgs a1,
                                                    int N, int K, int mode) {
    __shared__ __align__(16) float As[2][16][68];
    __shared__ __align__(16) float Ws[2][16][68];

    GemmArgs ga = (blockIdx.z == 0) ? a0 : a1;
    const float* __restrict__ A = ga.A;
    const float* __restrict__ W = ga.W;

    int bm = blockIdx.y * 64;
    int bn = blockIdx.x * 64;
    int tx = threadIdx.x;      // 0..255
    int tr = tx >> 4;          // 0..15
    int tc = tx & 15;          // 0..15

    int rowi = tx >> 2;        // 0..63  (loader row within tile)
    int k4   = tx & 3;         // 0..3   (loader float4 column group)

    const float* Arow = A + (size_t)(bm + rowi) * K + k4 * 4;
    const float* Wrow = W + (size_t)(bn + rowi) * K + k4 * 4;

    float scaleA = 1.0f;
    if (ga.divA) scaleA = 1.0f / fmaxf(g_cnt[bm + rowi], 1.0f);

    float acc[4][4];
#pragma unroll
    for (int i = 0; i < 4; i++)
#pragma unroll
        for (int j = 0; j < 4; j++) acc[i][j] = 0.0f;

    // prologue: load K-tile 0
    {
        float4 ra = *reinterpret_cast<const float4*>(Arow);
        float4 rw = *reinterpret_cast<const float4*>(Wrow);
        ra.x *= scaleA; ra.y *= scaleA; ra.z *= scaleA; ra.w *= scaleA;
        As[0][k4 * 4 + 0][rowi] = ra.x;
        As[0][k4 * 4 + 1][rowi] = ra.y;
        As[0][k4 * 4 + 2][rowi] = ra.z;
        As[0][k4 * 4 + 3][rowi] = ra.w;
        Ws[0][k4 * 4 + 0][rowi] = rw.x;
        Ws[0][k4 * 4 + 1][rowi] = rw.y;
        Ws[0][k4 * 4 + 2][rowi] = rw.z;
        Ws[0][k4 * 4 + 3][rowi] = rw.w;
    }
    __syncthreads();

    int nt = K >> 4;
    int buf = 0;
    for (int t = 0; t < nt; t++) {
        float4 na, nw;
        bool more = (t + 1 < nt);
        if (more) {
            na = *reinterpret_cast<const float4*>(Arow + (t + 1) * 16);
            nw = *reinterpret_cast<const float4*>(Wrow + (t + 1) * 16);
        }
#pragma unroll
        for (int kk = 0; kk < 16; kk++) {
            float4 a = *reinterpret_cast<const float4*>(&As[buf][kk][tr * 4]);
            float4 b = *reinterpret_cast<const float4*>(&Ws[buf][kk][tc * 4]);
            acc[0][0] = fmaf(a.x, b.x, acc[0][0]);
            acc[0][1] = fmaf(a.x, b.y, acc[0][1]);
            acc[0][2] = fmaf(a.x, b.z, acc[0][2]);
            acc[0][3] = fmaf(a.x, b.w, acc[0][3]);
            acc[1][0] = fmaf(a.y, b.x, acc[1][0]);
            acc[1][1] = fmaf(a.y, b.y, acc[1][1]);
            acc[1][2] = fmaf(a.y, b.z, acc[1][2]);
            acc[1][3] = fmaf(a.y, b.w, acc[1][3]);
            acc[2][0] = fmaf(a.z, b.x, acc[2][0]);
            acc[2][1] = fmaf(a.z, b.y, acc[2][1]);
            acc[2][2] = fmaf(a.z, b.z, acc[2][2]);
            acc[2][3] = fmaf(a.z, b.w, acc[2][3]);
            acc[3][0] = fmaf(a.w, b.x, acc[3][0]);
            acc[3][1] = fmaf(a.w, b.y, acc[3][1]);
            acc[3][2] = fmaf(a.w, b.z, acc[3][2]);
            acc[3][3] = fmaf(a.w, b.w, acc[3][3]);
        }
        if (more) {
            int nb = buf ^ 1;
            na.x *= scaleA; na.y *= scaleA; na.z *= scaleA; na.w *= scaleA;
            As[nb][k4 * 4 + 0][rowi] = na.x;
            As[nb][k4 * 4 + 1][rowi] = na.y;
            As[nb][k4 * 4 + 2][rowi] = na.z;
            As[nb][k4 * 4 + 3][rowi] = na.w;
            Ws[nb][k4 * 4 + 0][rowi] = nw.x;
            Ws[nb][k4 * 4 + 1][rowi] = nw.y;
            Ws[nb][k4 * 4 + 2][rowi] = nw.z;
            Ws[nb][k4 * 4 + 3][rowi] = nw.w;
            __syncthreads();
            buf = nb;
        }
    }

    // epilogue
    if (mode == 2) {
        // fused scatter-add of messages into segment sums
#pragma unroll
        for (int i = 0; i < 4; i++) {
            int r = bm + tr * 4 + i;
            int node = ga.sidx[r];
            float* dst = g_sums + (size_t)node * DIM;
#pragma unroll
            for (int j = 0; j < 4; j++) {
                int c = bn + tc * 4 + j;
                atomicAdd(&dst[c], acc[i][j] + ga.bias[c]);
            }
        }
    } else {
#pragma unroll
        for (int i = 0; i < 4; i++) {
            int r = bm + tr * 4 + i;
#pragma unroll
            for (int j = 0; j < 4; j++) {
                int c = bn + tc * 4 + j;
                float v = acc[i][j] + ga.bias[c];
                if (mode == 1) v = fmaxf(v, 0.0f);
                ga.C[(size_t)r * N + c] = v;
            }
        }
    }
}

// ---------------- GRU elementwise + touched mask ----------------
// One thread per float4. grid = NND*DIM/4/256 blocks.
__global__ void gru_kernel(const float* __restrict__ memory,
                           float* __restrict__ out) {
    int gid = blockIdx.x * blockDim.x + threadIdx.x;   // 0..65535
    int n  = gid >> 6;
    int d4 = gid & 63;

    const float4* GIr = reinterpret_cast<const float4*>(g_GI) + (size_t)n * (K3 / 4);
    const float4* GHr = reinterpret_cast<const float4*>(g_GH) + (size_t)n * (K3 / 4);
    float4 ir  = GIr[d4];
    float4 iz  = GIr[64 + d4];
    float4 in_ = GIr[128 + d4];
    float4 hr  = GHr[d4];
    float4 hz  = GHr[64 + d4];
    float4 hn  = GHr[128 + d4];
    float4 h = reinterpret_cast<const float4*>(memory)[(size_t)n * 64 + d4];

    bool touched = g_cnt[n] > 0.0f;
    float4 o;
    {
        float r = 1.0f / (1.0f + expf(-(ir.x + hr.x)));
        float z = 1.0f / (1.0f + expf(-(iz.x + hz.x)));
        float nn = tanhf(in_.x + r * hn.x);
        o.x = touched ? ((1.0f - z) * nn + z * h.x) : h.x;
    }
    {
        float r = 1.0f / (1.0f + expf(-(ir.y + hr.y)));
        float z = 1.0f / (1.0f + expf(-(iz.y + hz.y)));
        float nn = tanhf(in_.y + r * hn.y);
        o.y = touched ? ((1.0f - z) * nn + z * h.y) : h.y;
    }
    {
        float r = 1.0f / (1.0f + expf(-(ir.z + hr.z)));
        float z = 1.0f / (1.0f + expf(-(iz.z + hz.z)));
        float nn = tanhf(in_.z + r * hn.z);
        o.z = touched ? ((1.0f - z) * nn + z * h.z) : h.z;
    }
    {
        float r = 1.0f / (1.0f + expf(-(ir.w + hr.w)));
        float z = 1.0f / (1.0f + expf(-(iz.w + hz.w)));
        float nn = tanhf(in_.w + r * hn.w);
        o.w = touched ? ((1.0f - z) * nn + z * h.w) : h.w;
    }
    reinterpret_cast<float4*>(out)[gid] = o;
}

// ---------------- host ----------------

extern "C" void kernel_launch(void* const* d_in, const int* in_sizes, int n_in,
                              void* d_out, int out_size) {
    const float* memory   = (const float*)d_in[0];
    const int*   source   = (const int*)d_in[1];
    const int*   target   = (const int*)d_in[2];
    const float* dtv      = (const float*)d_in[3];
    const float* src_w1   = (const float*)d_in[4];
    const float* src_b1   = (const float*)d_in[5];
    const float* src_w2   = (const float*)d_in[6];
    const float* src_b2   = (const float*)d_in[7];
    const float* tar_w1   = (const float*)d_in[8];
    const float* tar_b1   = (const float*)d_in[9];
    const float* tar_w2   = (const float*)d_in[10];
    const float* tar_b2   = (const float*)d_in[11];
    const float* gru_wih  = (const float*)d_in[12];
    const float* gru_whh  = (const float*)d_in[13];
    const float* gru_bih  = (const float*)d_in[14];
    const float* gru_bhh  = (const float*)d_in[15];
    float* out = (float*)d_out;

    static float *pXsrc = nullptr, *pXtar, *pH0, *pH1, *pSums, *pCnt, *pGI, *pGH;
    if (!pXsrc) {
        cudaGetSymbolAddress((void**)&pXsrc, g_Xsrc);
        cudaGetSymbolAddress((void**)&pXtar, g_Xtar);
        cudaGetSymbolAddress((void**)&pH0,   g_H0);
        cudaGetSymbolAddress((void**)&pH1,   g_H1);
        cudaGetSymbolAddress((void**)&pSums, g_sums);
        cudaGetSymbolAddress((void**)&pCnt,  g_cnt);
        cudaGetSymbolAddress((void**)&pGI,   g_GI);
        cudaGetSymbolAddress((void**)&pGH,   g_GH);
    }

    // 1. zero sums + counts (memset nodes)
    cudaMemsetAsync(pSums, 0, (size_t)NND * DIM * sizeof(float));
    cudaMemsetAsync(pCnt,  0, (size_t)NND * sizeof(float));

    // 2. gather MLP inputs + counts
    gather_kernel<<<BSZ, 256>>>(memory, source, target, dtv);

    // 3. hidden = relu(X @ W1^T + b1)   [M=1024, N=256, K=768], batched src/tar
    {
        GemmArgs a0{pXsrc, src_w1, src_b1, pH0, nullptr, 0};
        GemmArgs a1{pXtar, tar_w1, tar_b1, pH1, nullptr, 0};
        dim3 grid(DIM / 64, BSZ / 64, 2);
        sgemm_kernel<<<grid, 256>>>(a0, a1, DIM, K3, /*mode=*/1);
    }

    // 4. msg = hidden @ W2^T + b2, fused scatter-add into g_sums
    {
        GemmArgs a0{pH0, src_w2, src_b2, nullptr, source, 0};
        GemmArgs a1{pH1, tar_w2, tar_b2, nullptr, target, 0};
        dim3 grid(DIM / 64, BSZ / 64, 2);
        sgemm_kernel<<<grid, 256>>>(a0, a1, DIM, DIM, /*mode=*/2);
    }

    // 5. GI = (sums/max(cnt,1)) @ wih^T + bih ; GH = memory @ whh^T + bhh
    {
        GemmArgs a0{pSums, gru_wih, gru_bih, pGI, nullptr, 1};
        GemmArgs a1{memory, gru_whh, gru_bhh, pGH, nullptr, 0};
        dim3 grid(K3 / 64, NND / 64, 2);
        sgemm_kernel<<<grid, 256>>>(a0, a1, K3, DIM, /*mode=*/0);
    }

    // 6. GRU elementwise + touched mask
    gru_kernel<<<(NND * DIM / 4) / 256, 256>>>(memory, out);
}

// round 11
// speedup vs baseline: 2.7402x; 2.7402x over previous
#include <cuda_runtime.h>
#include <cstdint>
#include <math.h>

#define BSZ 1024      // batch (edge events)
#define NND 1024      // nodes
#define DIM 256       // feature dim
#define K3  768       // 3*DIM

// GEMM tiling
#define BM 64
#define BN 64
#define BKK 32        // K per stage
#define SSTR 36       // smem row stride (floats): conflict-free + 16B aligned rows

// ---------------- scratch (device globals; no allocation) ----------------
__device__ __align__(16) float g_Xsrc[BSZ * K3];
__device__ __align__(16) float g_Xtar[BSZ * K3];
__device__ __align__(16) float g_H0[BSZ * DIM];
__device__ __align__(16) float g_H1[BSZ * DIM];
__device__ __align__(16) float g_sums[NND * DIM];
__device__ __align__(16) float g_cnt[NND];
__device__ __align__(16) float g_GI[NND * K3];
__device__ __align__(16) float g_GH[NND * K3];

// ---------------- PTX helpers ----------------
__device__ __forceinline__ uint32_t smem_u32(const void* p) {
    uint32_t a;
    asm("{ .reg .u64 t; cvta.to.shared.u64 t, %1; cvt.u32.u64 %0, t; }" : "=r"(a) : "l"(p));
    return a;
}
__device__ __forceinline__ uint32_t f2tf32(float x) {
    uint32_t r;
    asm("cvt.rna.tf32.f32 %0, %1;" : "=r"(r) : "f"(x));
    return r;
}
#define CP16(dst, src) \
    asm volatile("cp.async.cg.shared.global [%0], [%1], 16;" :: "r"(dst), "l"(src))
#define CP_COMMIT() asm volatile("cp.async.commit_group;" ::: "memory")
#define CP_WAIT0()  asm volatile("cp.async.wait_group 0;" ::: "memory")
#define CP_WAIT1()  asm volatile("cp.async.wait_group 1;" ::: "memory")

__device__ __forceinline__ void mma_tf32(float* c, const uint32_t* a, const uint32_t* b) {
    asm volatile(
        "mma.sync.aligned.m16n8k8.row.col.f32.tf32.tf32.f32 "
        "{%0,%1,%2,%3}, {%4,%5,%6,%7}, {%8,%9}, {%0,%1,%2,%3};"
        : "+f"(c[0]), "+f"(c[1]), "+f"(c[2]), "+f"(c[3])
        : "r"(a[0]), "r"(a[1]), "r"(a[2]), "r"(a[3]), "r"(b[0]), "r"(b[1]));
}

// ---------------- gather: build MLP inputs + counts ----------------
__global__ void gather_kernel(const float* __restrict__ memory,
                              const int* __restrict__ src,
                              const int* __restrict__ tgt,
                              const float* __restrict__ dtv) {
    int b = blockIdx.x;
    int t = threadIdx.x;
    int seg = t >> 6;
    int v   = t & 63;
    int s = src[b];
    int g = tgt[b];
    float4* Xs4 = reinterpret_cast<float4*>(g_Xsrc) + (size_t)b * (K3 / 4);
    float4* Xt4 = reinterpret_cast<float4*>(g_Xtar) + (size_t)b * (K3 / 4);
    if (seg == 0) {
        float4 m = reinterpret_cast<const float4*>(memory)[(size_t)s * 64 + v];
        Xs4[v] = m;  Xt4[64 + v] = m;
    } else if (seg == 1) {
        float4 m = reinterpret_cast<const float4*>(memory)[(size_t)g * 64 + v];
        Xs4[64 + v] = m;  Xt4[v] = m;
    } else if (seg == 2) {
        float4 d = reinterpret_cast<const float4*>(dtv)[((size_t)b * NND + s) * 64 + v];
        Xs4[128 + v] = d;
    } else {
        float4 d = reinterpret_cast<const float4*>(dtv)[((size_t)b * NND + g) * 64 + v];
        Xt4[128 + v] = d;
    }
    if (t == 0) {
        atomicAdd(&g_cnt[s], 1.0f);
        atomicAdd(&g_cnt[g], 1.0f);
    }
}

// ---------------- tf32 mma.sync GEMM ----------------
// C[M,N] = A[M,K] @ W[N,K]^T + bias[N]
// mode 0: store, 1: relu+store, 2: atomicAdd into g_sums[sidx[row]*DIM + col]
// divA: scale output row r by 1/max(g_cnt[bm+r],1) (fused agg divide, epilogue)
struct GemmArgs {
    const float* A;
    const float* W;
    const float* bias;
    float* C;
    const int* sidx;
    int divA;
};

__global__ __launch_bounds__(128) void mma_gemm_kernel(GemmArgs a0, GemmArgs a1,
                                                       int N, int K, int mode) {
    __shared__ __align__(16) float As[2][BM][SSTR];
    __shared__ __align__(16) float Bs[2][BN][SSTR];

    GemmArgs ga = (blockIdx.z == 0) ? a0 : a1;
    const float* __restrict__ A = ga.A;
    const float* __restrict__ W = ga.W;

    int bm = blockIdx.y * BM;
    int bn = blockIdx.x * BN;
    int tid = threadIdx.x;
    int wid = tid >> 5;
    int lane = tid & 31;
    int gidq = lane >> 2;   // group id 0..7
    int tig  = lane & 3;    // thread in group 0..3
    int wm = wid & 1;       // warp m (2)
    int wn = wid >> 1;      // warp n (2)

    float acc[2][4][4];
#pragma unroll
    for (int i = 0; i < 2; i++)
#pragma unroll
        for (int j = 0; j < 4; j++)
#pragma unroll
            for (int l = 0; l < 4; l++) acc[i][j][l] = 0.0f;

    int nst = K >> 5;   // stages of BKK=32

    // loader: 64 rows x 8 chunks(16B) per tile = 512 chunks; 128 thr x 4
    // stage s -> global k offset s*32
    // row = cid>>3, ch = cid&7
    // prologue
    {
        const float* Ab = A + (size_t)bm * K;
        const float* Wb = W + (size_t)bn * K;
#pragma unroll
        for (int i = 0; i < 4; i++) {
            int cid = tid + i * 128;
            int row = cid >> 3;
            int ch  = cid & 7;
            CP16(smem_u32(&As[0][row][ch * 4]), Ab + (size_t)row * K + ch * 4);
            CP16(smem_u32(&Bs[0][row][ch * 4]), Wb + (size_t)row * K + ch * 4);
        }
        CP_COMMIT();
    }

    int buf = 0;
    for (int s = 0; s < nst; s++) {
        if (s + 1 < nst) {
            const float* Ab = A + (size_t)bm * K + (s + 1) * BKK;
            const float* Wb = W + (size_t)bn * K + (s + 1) * BKK;
            int nb = buf ^ 1;
#pragma unroll
            for (int i = 0; i < 4; i++) {
                int cid = tid + i * 128;
                int row = cid >> 3;
                int ch  = cid & 7;
                CP16(smem_u32(&As[nb][row][ch * 4]), Ab + (size_t)row * K + ch * 4);
                CP16(smem_u32(&Bs[nb][row][ch * 4]), Wb + (size_t)row * K + ch * 4);
            }
            CP_COMMIT();
            CP_WAIT1();
        } else {
            CP_WAIT0();
        }
        __syncthreads();

        // compute this stage: 4 k-steps of 8
#pragma unroll
        for (int ks = 0; ks < 4; ks++) {
            int k0 = ks * 8;
            uint32_t afr[2][4];
#pragma unroll
            for (int ma = 0; ma < 2; ma++) {
                int r = wm * 32 + ma * 16 + gidq;
                afr[ma][0] = f2tf32(As[buf][r][k0 + tig]);
                afr[ma][1] = f2tf32(As[buf][r + 8][k0 + tig]);
                afr[ma][2] = f2tf32(As[buf][r][k0 + tig + 4]);
                afr[ma][3] = f2tf32(As[buf][r + 8][k0 + tig + 4]);
            }
            uint32_t bfr[4][2];
#pragma unroll
            for (int na = 0; na < 4; na++) {
                int c = wn * 32 + na * 8 + gidq;
                bfr[na][0] = f2tf32(Bs[buf][c][k0 + tig]);
                bfr[na][1] = f2tf32(Bs[buf][c][k0 + tig + 4]);
            }
#pragma unroll
            for (int ma = 0; ma < 2; ma++)
#pragma unroll
                for (int na = 0; na < 4; na++)
                    mma_tf32(acc[ma][na], afr[ma], bfr[na]);
        }
        __syncthreads();
        buf ^= 1;
    }

    // ---- epilogue: bias / relu / divA-scale / scatter ----
#pragma unroll
    for (int ma = 0; ma < 2; ma++) {
        int rl0 = wm * 32 + ma * 16 + gidq;   // local rows
        int rl1 = rl0 + 8;
        float s0 = 1.0f, s1 = 1.0f;
        if (ga.divA) {
            s0 = 1.0f / fmaxf(g_cnt[bm + rl0], 1.0f);
            s1 = 1.0f / fmaxf(g_cnt[bm + rl1], 1.0f);
        }
#pragma unroll
        for (int na = 0; na < 4; na++) {
            int cl = wn * 32 + na * 8 + tig * 2;
            int cg = bn + cl;
            float b0v = ga.bias[cg];
            float b1v = ga.bias[cg + 1];
            float v00 = acc[ma][na][0] * s0 + b0v;
            float v01 = acc[ma][na][1] * s0 + b1v;
            float v10 = acc[ma][na][2] * s1 + b0v;
            float v11 = acc[ma][na][3] * s1 + b1v;
            if (mode == 1) {
                v00 = fmaxf(v00, 0.0f); v01 = fmaxf(v01, 0.0f);
                v10 = fmaxf(v10, 0.0f); v11 = fmaxf(v11, 0.0f);
            }
            if (mode == 2) {
                int n0 = ga.sidx[bm + rl0];
                int n1 = ga.sidx[bm + rl1];
                atomicAdd(&g_sums[(size_t)n0 * DIM + cg],     v00);
                atomicAdd(&g_sums[(size_t)n0 * DIM + cg + 1], v01);
                atomicAdd(&g_sums[(size_t)n1 * DIM + cg],     v10);
                atomicAdd(&g_sums[(size_t)n1 * DIM + cg + 1], v11);
            } else {
                *reinterpret_cast<float2*>(ga.C + (size_t)(bm + rl0) * N + cg) =
                    make_float2(v00, v01);
                *reinterpret_cast<float2*>(ga.C + (size_t)(bm + rl1) * N + cg) =
                    make_float2(v10, v11);
            }
        }
    }
}

// ---------------- GRU elementwise + touched mask ----------------
__global__ void gru_kernel(const float* __restrict__ memory,
                           float* __restrict__ out) {
    int gid = blockIdx.x * blockDim.x + threadIdx.x;
    int n  = gid >> 6;
    int d4 = gid & 63;
    const float4* GIr = reinterpret_cast<const float4*>(g_GI) + (size_t)n * (K3 / 4);
    const float4* GHr = reinterpret_cast<const float4*>(g_GH) + (size_t)n * (K3 / 4);
    float4 ir  = GIr[d4];
    float4 iz  = GIr[64 + d4];
    float4 in_ = GIr[128 + d4];
    float4 hr  = GHr[d4];
    float4 hz  = GHr[64 + d4];
    float4 hn  = GHr[128 + d4];
    float4 h = reinterpret_cast<const float4*>(memory)[(size_t)n * 64 + d4];
    bool touched = g_cnt[n] > 0.0f;
    float4 o;
    {
        float r = 1.0f / (1.0f + expf(-(ir.x + hr.x)));
        float z = 1.0f / (1.0f + expf(-(iz.x + hz.x)));
        float nn = tanhf(in_.x + r * hn.x);
        o.x = touched ? ((1.0f - z) * nn + z * h.x) : h.x;
    }
    {
        float r = 1.0f / (1.0f + expf(-(ir.y + hr.y)));
        float z = 1.0f / (1.0f + expf(-(iz.y + hz.y)));
        float nn = tanhf(in_.y + r * hn.y);
        o.y = touched ? ((1.0f - z) * nn + z * h.y) : h.y;
    }
    {
        float r = 1.0f / (1.0f + expf(-(ir.z + hr.z)));
        float z = 1.0f / (1.0f + expf(-(iz.z + hz.z)));
        float nn = tanhf(in_.z + r * hn.z);
        o.z = touched ? ((1.0f - z) * nn + z * h.z) : h.z;
    }
    {
        float r = 1.0f / (1.0f + expf(-(ir.w + hr.w)));
        float z = 1.0f / (1.0f + expf(-(iz.w + hz.w)));
        float nn = tanhf(in_.w + r * hn.w);
        o.w = touched ? ((1.0f - z) * nn + z * h.w) : h.w;
    }
    reinterpret_cast<float4*>(out)[gid] = o;
}

// ---------------- host ----------------

extern "C" void kernel_launch(void* const* d_in, const int* in_sizes, int n_in,
                              void* d_out, int out_size) {
    const float* memory   = (const float*)d_in[0];
    const int*   source   = (const int*)d_in[1];
    const int*   target   = (const int*)d_in[2];
    const float* dtv      = (const float*)d_in[3];
    const float* src_w1   = (const float*)d_in[4];
    const float* src_b1   = (const float*)d_in[5];
    const float* src_w2   = (const float*)d_in[6];
    const float* src_b2   = (const float*)d_in[7];
    const float* tar_w1   = (const float*)d_in[8];
    const float* tar_b1   = (const float*)d_in[9];
    const float* tar_w2   = (const float*)d_in[10];
    const float* tar_b2   = (const float*)d_in[11];
    const float* gru_wih  = (const float*)d_in[12];
    const float* gru_whh  = (const float*)d_in[13];
    const float* gru_bih  = (const float*)d_in[14];
    const float* gru_bhh  = (const float*)d_in[15];
    float* out = (float*)d_out;

    static float *pXsrc = nullptr, *pXtar, *pH0, *pH1, *pSums, *pCnt, *pGI, *pGH;
    if (!pXsrc) {
        cudaGetSymbolAddress((void**)&pXsrc, g_Xsrc);
        cudaGetSymbolAddress((void**)&pXtar, g_Xtar);
        cudaGetSymbolAddress((void**)&pH0,   g_H0);
        cudaGetSymbolAddress((void**)&pH1,   g_H1);
        cudaGetSymbolAddress((void**)&pSums, g_sums);
        cudaGetSymbolAddress((void**)&pCnt,  g_cnt);
        cudaGetSymbolAddress((void**)&pGI,   g_GI);
        cudaGetSymbolAddress((void**)&pGH,   g_GH);
    }

    // 1. zero sums + counts
    cudaMemsetAsync(pSums, 0, (size_t)NND * DIM * sizeof(float));
    cudaMemsetAsync(pCnt,  0, (size_t)NND * sizeof(float));

    // 2. gather MLP inputs + counts
    gather_kernel<<<BSZ, 256>>>(memory, source, target, dtv);

    // 3. hidden = relu(X @ W1^T + b1)   [1024 x 256 x 768], batched src/tar
    {
        GemmArgs a0{pXsrc, src_w1, src_b1, pH0, nullptr, 0};
        GemmArgs a1{pXtar, tar_w1, tar_b1, pH1, nullptr, 0};
        dim3 grid(DIM / BN, BSZ / BM, 2);
        mma_gemm_kernel<<<grid, 128>>>(a0, a1, DIM, K3, 1);
    }

    // 4. msg = hidden @ W2^T + b2, fused scatter-add into g_sums
    {
        GemmArgs a0{pH0, src_w2, src_b2, nullptr, source, 0};
        GemmArgs a1{pH1, tar_w2, tar_b2, nullptr, target, 0};
        dim3 grid(DIM / BN, BSZ / BM, 2);
        mma_gemm_kernel<<<grid, 128>>>(a0, a1, DIM, DIM, 2);
    }

    // 5. GI = (sums/max(cnt,1)) @ wih^T + bih ; GH = memory @ whh^T + bhh
    {
        GemmArgs a0{pSums, gru_wih, gru_bih, pGI, nullptr, 1};
        GemmArgs a1{memory, gru_whh, gru_bhh, pGH, nullptr, 0};
        dim3 grid(K3 / BN, NND / BM, 2);
        mma_gemm_kernel<<<grid, 128>>>(a0, a1, K3, DIM, 0);
    }

    // 6. GRU elementwise + touched mask
    gru_kernel<<<(NND * DIM / 4) / 256, 256>>>(memory, out);
}